// round 7
// baseline (speedup 1.0000x reference)
#include <cuda_runtime.h>
#include <math.h>

#define BATCH 16384
#define NUM_CLASSES 1604
#define C4 (NUM_CLASSES / 4)      // 401 float4 per row
#define THREADS 256
#define WARPS 8
#define EPS 1e-6f

// Device-global scratch (allocation-free).
__device__ int g_counts[NUM_CLASSES];
__device__ int g_off[NUM_CLASSES];
__device__ int g_cursor[NUM_CLASSES];
__device__ int g_order[BATCH];

// ---------------- pass 0: zero counters + output ----------------
__global__ void zero_kernel(float* out) {
    int i = blockIdx.x * blockDim.x + threadIdx.x;
    if (i < NUM_CLASSES) g_counts[i] = 0;
    if (i == 0) out[0] = 0.0f;
}

// ---------------- pass 1: histogram of targets ----------------
__global__ void hist_kernel(const int* __restrict__ targets) {
    int b = blockIdx.x * blockDim.x + threadIdx.x;
    if (b < BATCH) atomicAdd(&g_counts[targets[b]], 1);
}

// ---------------- pass 2: exclusive scan (1 block, 512 thr, 4 elem/thr) ---
__global__ void scan_kernel() {
    const int t = threadIdx.x;            // 0..511, covers 2048 >= 1604
    const int lane = t & 31, wid = t >> 5;
    const int base = t * 4;
    int c[4];
    #pragma unroll
    for (int j = 0; j < 4; j++)
        c[j] = (base + j < NUM_CLASSES) ? g_counts[base + j] : 0;
    int local = c[0] + c[1] + c[2] + c[3];

    int v = local;                        // inclusive warp scan
    #pragma unroll
    for (int o = 1; o < 32; o <<= 1) {
        int n = __shfl_up_sync(0xFFFFFFFFu, v, o);
        if (lane >= o) v += n;
    }
    __shared__ int wsum[16];
    if (lane == 31) wsum[wid] = v;
    __syncthreads();
    if (wid == 0) {
        int w = (lane < 16) ? wsum[lane] : 0;
        #pragma unroll
        for (int o = 1; o < 16; o <<= 1) {
            int n = __shfl_up_sync(0xFFFFFFFFu, w, o);
            if (lane >= o) w += n;
        }
        if (lane < 16) wsum[lane] = w;    // inclusive warp totals
    }
    __syncthreads();
    int warp_excl = (wid > 0) ? wsum[wid - 1] : 0;
    int run = warp_excl + (v - local);    // exclusive prefix for this chunk
    #pragma unroll
    for (int j = 0; j < 4; j++) {
        if (base + j < NUM_CLASSES) { g_off[base + j] = run; g_cursor[base + j] = run; }
        run += c[j];
    }
}

// ---------------- pass 3: scatter sample ids by class ----------------
__global__ void scatter_kernel(const int* __restrict__ targets) {
    int b = blockIdx.x * blockDim.x + threadIdx.x;
    if (b < BATCH) {
        int t = targets[b];
        int pos = atomicAdd(&g_cursor[t], 1);
        g_order[pos] = b;
    }
}

// ---------------- pass 4: main loss, one block per class ----------------
// s[c] row loaded to SMEM once per class (~10 samples reuse it), so the
// per-sample s traffic moves off the L2/LTS path entirely.
// No max-subtraction: sigma is shift-invariant; EPS perturbation ~1e-7 rel
// (measured margin at R5: rel_err 5e-7 vs 1e-3 gate).
__global__ __launch_bounds__(THREADS, 8)
void seesaw_main_kernel(const float* __restrict__ logits,
                        const float* __restrict__ s,
                        float* __restrict__ out) {
    const int c = blockIdx.x;
    const int cnt = g_counts[c];
    if (cnt == 0) return;                 // uniform branch: whole block exits

    __shared__ float s_sm[NUM_CLASSES];
    __shared__ float sh_total;
    const int tid = threadIdx.x;
    const int warp = tid >> 5;
    const int lane = tid & 31;

    if (tid == 0) sh_total = 0.0f;
    {   // cooperative s-row load (float4, fully coalesced)
        const float4* __restrict__ srow =
            reinterpret_cast<const float4*>(s + (size_t)c * NUM_CLASSES);
        float4* s4 = reinterpret_cast<float4*>(s_sm);
        for (int i = tid; i < C4; i += THREADS) s4[i] = srow[i];
    }
    __syncthreads();

    const float4* s4 = reinterpret_cast<const float4*>(s_sm);
    const int off = g_off[c];
    float wloss = 0.0f;

    for (int k = warp; k < cnt; k += WARPS) {
        const int b = g_order[off + k];
        const float4* __restrict__ lrow =
            reinterpret_cast<const float4*>(logits + (size_t)b * NUM_CLASSES);

        // denom = sum_j s[c,j]*exp(x_j); j==t term equals num_t (s[c,c]==1).
        float sum = 0.0f;
        #pragma unroll 4
        for (int i = lane; i < C4; i += 32) {
            float4 x = lrow[i];
            float4 w = s4[i];
            sum += w.x * __expf(x.x) + w.y * __expf(x.y)
                 + w.z * __expf(x.z) + w.w * __expf(x.w);
        }
        #pragma unroll
        for (int o = 16; o > 0; o >>= 1)
            sum += __shfl_xor_sync(0xFFFFFFFFu, sum, o);

        if (lane == 0) {
            float xt = logits[(size_t)b * NUM_CLASSES + c];
            float num_t = __expf(xt);
            float sigma = num_t / (sum + EPS);
            wloss += -__logf(sigma + EPS);
        }
    }

    if (lane == 0 && wloss != 0.0f) atomicAdd(&sh_total, wloss);
    __syncthreads();
    if (tid == 0) atomicAdd(out, sh_total * (1.0f / (float)BATCH));
}

extern "C" void kernel_launch(void* const* d_in, const int* in_sizes, int n_in,
                              void* d_out, int out_size) {
    const float* logits  = (const float*)d_in[0];
    const float* s       = (const float*)d_in[1];
    const int*   targets = (const int*)d_in[2];
    float* out = (float*)d_out;

    zero_kernel   <<<(NUM_CLASSES + 255) / 256, 256>>>(out);
    hist_kernel   <<<BATCH / 256, 256>>>(targets);
    scan_kernel   <<<1, 512>>>();
    scatter_kernel<<<BATCH / 256, 256>>>(targets);
    seesaw_main_kernel<<<NUM_CLASSES, THREADS>>>(logits, s, out);
}